// round 9
// baseline (speedup 1.0000x reference)
#include <cuda_runtime.h>
#include <cuda_bf16.h>
#include <math.h>
#include <stdint.h>

// ---------------------------------------------------------------- shapes
constexpr int Bn = 16, Tn = 512, Hn = 512, Vn = 4096, Ln = 64, Jn = 66;
constexpr int Mn = Bn * Tn;            // 8192 GEMM rows
constexpr int Smax = 2 * Ln + 1;       // 129 CTC states
constexpr float NEGF = -1e30f;
constexpr float LOG2E = 1.4426950408889634f;
constexpr float LN2 = 0.6931471805599453f;

// ---------------------------------------------------------------- scratch
__device__ __nv_bfloat16 g_Abf[(size_t)Mn * Hn];    // 8 MB
__device__ __nv_bfloat16 g_Bbf[(size_t)Vn * Hn];    // 4 MB  W^T [V,K] K-major
__device__ float2        g_part[(size_t)Mn * 128];  // per-row (max,sumexp) partials
__device__ float         g_gath[(size_t)Mn * Jn];   // gathered logits at label ids
__device__ float         g_emit[(size_t)Mn * Jn];   // log2-domain emissions
__device__ int           g_rep[Bn * Jn];            // duplicate-label representative
__device__ float         g_ll[Bn];
__device__ int           g_ctr;

// ---------------------------------------------------------------- helpers
__device__ __forceinline__ uint32_t smem_u32(const void* p) {
    uint32_t a;
    asm("{ .reg .u64 t; cvta.to.shared.u64 t, %1; cvt.u32.u64 %0, t; }" : "=r"(a) : "l"(p));
    return a;
}
__device__ __forceinline__ void ldm_x4(uint32_t* r, uint32_t addr) {
    asm volatile("ldmatrix.sync.aligned.m8n8.x4.shared.b16 {%0,%1,%2,%3}, [%4];"
                 : "=r"(r[0]), "=r"(r[1]), "=r"(r[2]), "=r"(r[3]) : "r"(addr));
}
__device__ __forceinline__ void ldm_x2(uint32_t* r, uint32_t addr) {
    asm volatile("ldmatrix.sync.aligned.m8n8.x2.shared.b16 {%0,%1}, [%2];"
                 : "=r"(r[0]), "=r"(r[1]) : "r"(addr));
}
__device__ __forceinline__ void mma_bf16(float* d, const uint32_t* a, const uint32_t* b) {
    asm volatile("mma.sync.aligned.m16n8k16.row.col.f32.bf16.bf16.f32 "
                 "{%0,%1,%2,%3}, {%4,%5,%6,%7}, {%8,%9}, {%0,%1,%2,%3};"
                 : "+f"(d[0]), "+f"(d[1]), "+f"(d[2]), "+f"(d[3])
                 : "r"(a[0]), "r"(a[1]), "r"(a[2]), "r"(a[3]), "r"(b[0]), "r"(b[1]));
}
__device__ __forceinline__ float ex2(float x) {
    float r; asm("ex2.approx.ftz.f32 %0, %1;" : "=f"(r) : "f"(x)); return r;
}
__device__ __forceinline__ float lg2(float x) {
    float r; asm("lg2.approx.f32 %0, %1;" : "=f"(r) : "f"(x)); return r;
}
#define CP_ASYNC16(dst, src) \
    asm volatile("cp.async.cg.shared.global [%0], [%1], 16;" :: "r"(dst), "l"(src) : "memory")
#define CP_COMMIT() asm volatile("cp.async.commit_group;" ::: "memory")
#define CP_WAIT2()  asm volatile("cp.async.wait_group 2;" ::: "memory")

// ---------------------------------------------------------------- fused preprocessing
__global__ __launch_bounds__(256) void prep_kernel(const float* __restrict__ hs,
                                                   const float* __restrict__ W,
                                                   const int* __restrict__ ys) {
    const int bid = blockIdx.x, tid = threadIdx.x;
    if (bid < 4096) {
        size_t i = (size_t)bid * 256 + tid;
        float4 v = ((const float4*)hs)[i];
        __nv_bfloat162 lo = __floats2bfloat162_rn(v.x, v.y);
        __nv_bfloat162 hi = __floats2bfloat162_rn(v.z, v.w);
        uint2 u;
        u.x = *(uint32_t*)&lo;
        u.y = *(uint32_t*)&hi;
        ((uint2*)g_Abf)[i] = u;
    } else if (bid < 6144) {
        __shared__ float tile[32][33];
        const int vb = bid - 4096;
        const int v0 = (vb & 127) * 32, k0 = (vb >> 7) * 32;
        const int tx = tid & 31, ty = tid >> 5;
#pragma unroll
        for (int j = 0; j < 4; j++)
            tile[ty + 8 * j][tx] = W[(size_t)(k0 + ty + 8 * j) * Vn + v0 + tx];
        __syncthreads();
#pragma unroll
        for (int j = 0; j < 4; j++) {
            int vl = ty + 8 * j;
            g_Bbf[(size_t)(v0 + vl) * Hn + k0 + tx] = __float2bfloat16(tile[tx][vl]);
        }
    } else if (bid < 6160) {
        const int b = bid - 6144;
        const int j = tid;
        if (j < 65) {
            const int vid = (j == 0) ? 0 : ys[b * Ln + j - 1];
            int r = j;
            for (int q = 0; q < j; q++) {
                const int vq = (q == 0) ? 0 : ys[b * Ln + q - 1];
                if (vq == vid) { r = q; break; }
            }
            g_rep[b * Jn + j] = r;
        }
    } else {
        if (tid == 0) g_ctr = 0;
    }
}

// ---------------------------------------------------------------- HMMA GEMM
// CTA tile 64x128, BK=32, 8 warps (warp tile 32x32), 4-stage cp.async, 3 CTAs/SM.
// Per stage: A[4 subs(16B)][64 rows] = 4KB at +0; B[4 subs][128 rows] = 8KB at +4096.
constexpr int STAGES = 4;
constexpr int STAGE_BYTES = 12288;
constexpr int GEMM_SMEM = STAGES * STAGE_BYTES;   // 48 KB

__global__ __launch_bounds__(256, 3) void gemm_mma_kernel(const int* __restrict__ ys,
                                                          const float* __restrict__ bias) {
    extern __shared__ __align__(1024) char sm[];
    __shared__ float sbias[128];
    __shared__ int stable[128];

    const int tid = threadIdx.x, w = tid >> 5, lane = tid & 31;
    const int bn = blockIdx.x * 128, bm = blockIdx.y * 64;
    const int b = blockIdx.y >> 3;   // 512/64 = 8 row-blocks per batch

    if (tid < 128) { sbias[tid] = bias[bn + tid]; stable[tid] = -1; }
    __syncthreads();
    if (tid == 0) {
        for (int j = 0; j < 65; j++) {
            const int vid = (j == 0) ? 0 : ys[b * Ln + j - 1];
            const int idx = vid - bn;
            if (idx >= 0 && idx < 128 && stable[idx] < 0) stable[idx] = j;
        }
    }

    // cp.async mapping
    const int arow = tid >> 2, akq = tid & 3;          // A: 1 x 16B per thread
    const int brow = tid >> 1, bq2 = (tid & 1) * 2;    // B: 2 x 16B per thread
    const __nv_bfloat16* gA = g_Abf + (size_t)(bm + arow) * Hn + akq * 8;
    const __nv_bfloat16* gB = g_Bbf + (size_t)(bn + brow) * Hn + bq2 * 8;
    const uint32_t smb = smem_u32(sm);
    const uint32_t stsA = smb + (uint32_t)akq * 1024 + (uint32_t)arow * 16;
    const uint32_t stsB = smb + 4096 + (uint32_t)bq2 * 2048 + (uint32_t)brow * 16;

    // ldmatrix bases (within a stage)
    const int wm = w >> 2, wn = w & 3;
    const uint32_t aBase = smb + (uint32_t)(wm * 32 + (lane & 15)) * 16 + (uint32_t)(lane >> 4) * 1024;
    const uint32_t bBase = smb + 4096 + (uint32_t)(wn * 32 + (lane & 7)) * 16 + (uint32_t)((lane >> 3) & 1) * 2048;

    float acc[2][4][4];
#pragma unroll
    for (int mi = 0; mi < 2; mi++)
#pragma unroll
        for (int ni = 0; ni < 4; ni++)
#pragma unroll
            for (int e = 0; e < 4; e++) acc[mi][ni][e] = 0.f;

    const int NC = Hn / 32;  // 16

#define ISSUE_STAGE(slot, c)                                                   \
    do {                                                                       \
        const uint32_t so = (uint32_t)(slot) * STAGE_BYTES;                    \
        CP_ASYNC16(stsA + so, gA + (c) * 32);                                  \
        CP_ASYNC16(stsB + so, gB + (c) * 32);                                  \
        CP_ASYNC16(stsB + so + 2048, gB + (c) * 32 + 8);                       \
    } while (0)

#pragma unroll
    for (int c = 0; c < 3; c++) { ISSUE_STAGE(c, c); CP_COMMIT(); }

    for (int c = 0; c < NC; c++) {
        CP_WAIT2();
        __syncthreads();
        if (c + 3 < NC) ISSUE_STAGE((c + 3) & (STAGES - 1), c + 3);
        CP_COMMIT();

        const uint32_t so = (uint32_t)(c & (STAGES - 1)) * STAGE_BYTES;
#pragma unroll
        for (int kk = 0; kk < 2; kk++) {
            uint32_t aF[2][4], bF[4][2];
#pragma unroll
            for (int mi = 0; mi < 2; mi++)
                ldm_x4(aF[mi], aBase + so + kk * 2048 + mi * 256);
#pragma unroll
            for (int ni = 0; ni < 4; ni++)
                ldm_x2(bF[ni], bBase + so + kk * 4096 + ni * 128);
#pragma unroll
            for (int mi = 0; mi < 2; mi++)
#pragma unroll
                for (int ni = 0; ni < 4; ni++)
                    mma_bf16(acc[mi][ni], aF[mi], bF[ni]);
        }
    }

    // ---- fused epilogue: bias, row (max,sumexp) partials, label gather
    const int tq = lane >> 2, lq = lane & 3;
#pragma unroll
    for (int mi = 0; mi < 2; mi++) {
#pragma unroll
        for (int h = 0; h < 2; h++) {
            const int rloc = wm * 32 + mi * 16 + h * 8 + tq;
            const size_t grow = (size_t)(bm + rloc);
            float v[8];
            float mx = -3.4e38f;
#pragma unroll
            for (int ni = 0; ni < 4; ni++)
#pragma unroll
                for (int e = 0; e < 2; e++) {
                    float f = acc[mi][ni][h * 2 + e] + sbias[wn * 32 + ni * 8 + lq * 2 + e];
                    v[ni * 2 + e] = f;
                    mx = fmaxf(mx, f);
                }
            float sum = 0.f;
#pragma unroll
            for (int i = 0; i < 8; i++) sum += __expf(v[i] - mx);
#pragma unroll
            for (int o = 1; o <= 2; o <<= 1) {
                float mo = __shfl_xor_sync(0xffffffffu, mx, o);
                float so2 = __shfl_xor_sync(0xffffffffu, sum, o);
                float m2 = fmaxf(mx, mo);
                sum = sum * __expf(mx - m2) + so2 * __expf(mo - m2);
                mx = m2;
            }
            if (lq == 0)
                g_part[grow * 128 + blockIdx.x * 4 + wn] = make_float2(mx, sum);
#pragma unroll
            for (int ni = 0; ni < 4; ni++)
#pragma unroll
                for (int e = 0; e < 2; e++) {
                    const int cidx = wn * 32 + ni * 8 + lq * 2 + e;
                    const int slot = stable[cidx];
                    if (slot >= 0) g_gath[grow * Jn + slot] = v[ni * 2 + e];
                }
        }
    }
}

// ---------------------------------------------------------------- LSE reduce + emit (log2 domain)
__global__ __launch_bounds__(256) void lse_emit_kernel() {
    const int warp = threadIdx.x >> 5, lane = threadIdx.x & 31;
    const size_t row = (size_t)blockIdx.x * 8 + warp;
    const int b = (int)(row >> 9);
    float2 p[4];
#pragma unroll
    for (int i = 0; i < 4; i++) p[i] = g_part[row * 128 + lane + 32 * i];
    float m = fmaxf(fmaxf(p[0].x, p[1].x), fmaxf(p[2].x, p[3].x));
#pragma unroll
    for (int o = 16; o > 0; o >>= 1) m = fmaxf(m, __shfl_xor_sync(0xffffffffu, m, o));
    float s = 0.f;
#pragma unroll
    for (int i = 0; i < 4; i++) s += p[i].y * __expf(p[i].x - m);
#pragma unroll
    for (int o = 16; o > 0; o >>= 1) s += __shfl_xor_sync(0xffffffffu, s, o);
    const float lse = m + __logf(s);
#pragma unroll
    for (int j = lane; j < 65; j += 32)
        g_emit[row * Jn + j] = (g_gath[row * Jn + g_rep[b * Jn + j]] - lse) * LOG2E;
}

// ---------------------------------------------------------------- CTC DP: halo-4 wavefront (R6 winner)
__global__ __launch_bounds__(160) void ctc_dp_kernel(const int* __restrict__ ys,
                                                     const int* __restrict__ hlen,
                                                     const int* __restrict__ ylen,
                                                     float* __restrict__ out) {
    extern __shared__ float sem[];   // staged log2-emissions [inlen][Jn]
    __shared__ float sbuf[2][20];    // ping-pong boundary: 4 values per warp
    __shared__ float sal[Smax + 12];

    const int b = blockIdx.x, tid = threadIdx.x;
    const int w = tid >> 5, lane = tid & 31;
    const int s = w * 28 + lane - 4;
    const int inlen = hlen[b];

    {
        const float2* src = (const float2*)(g_emit + (size_t)b * Tn * Jn);
        float2* dst = (float2*)sem;
        const int n2 = inlen * (Jn / 2);
        for (int i = tid; i < n2; i += 160) dst[i] = src[i];
    }

    int jj = 0;
    bool skipv = false;
    if (s >= 0 && s < Smax && (s & 1)) {
        const int li = (s - 1) >> 1;
        jj = li + 1;
        const int lab = ys[b * Ln + li];
        if (s >= 3) skipv = (lab != 0) && (lab != ys[b * Ln + li - 1]);
    }
    __syncthreads();

    float a = (s == 0) ? sem[0] : (s == 1) ? sem[1] : NEGF;
    int pb = 0;
    if (lane >= 28) sbuf[0][w * 4 + lane - 28] = a;
    __syncthreads();

    for (int t = 1; t < inlen; t += 2) {
        if (lane < 4) a = (w > 0) ? sbuf[pb][(w - 1) * 4 + lane] : NEGF;
        {
            const float e = sem[t * Jn + jj];
            const float up1 = __shfl_up_sync(0xffffffffu, a, 1);
            const float up2 = __shfl_up_sync(0xffffffffu, a, 2);
            const float am2 = skipv ? up2 : NEGF;
            const float m = fmaxf(fmaxf(a, up1), am2);
            a = m + lg2(ex2(a - m) + ex2(up1 - m) + ex2(am2 - m)) + e;
        }
        if (t + 1 < inlen) {
            const float e = sem[(t + 1) * Jn + jj];
            const float up1 = __shfl_up_sync(0xffffffffu, a, 1);
            const float up2 = __shfl_up_sync(0xffffffffu, a, 2);
            const float am2 = skipv ? up2 : NEGF;
            const float m = fmaxf(fmaxf(a, up1), am2);
            a = m + lg2(ex2(a - m) + ex2(up1 - m) + ex2(am2 - m)) + e;
        }
        pb ^= 1;
        if (lane >= 28) sbuf[pb][w * 4 + lane - 28] = a;
        __syncthreads();
    }

    if (lane >= 4 && s < Smax) sal[s] = a;
    __syncthreads();
    if (tid == 0) {
        const int s2 = 2 * ylen[b];
        const float x = sal[s2], y = sal[s2 - 1];
        const float m = fmaxf(x, y), d = fminf(x, y) - m;
        g_ll[b] = -(m + lg2(1.f + ex2(d))) * LN2;
        __threadfence();
        const int done = atomicAdd(&g_ctr, 1);
        if (done == Bn - 1) {
            float acc = 0.f;
#pragma unroll
            for (int i = 0; i < Bn; i++) acc += g_ll[i];
            out[0] = acc / (float)Bn;
        }
    }
}

// ----------------------------------------------------------------
extern "C" void kernel_launch(void* const* d_in, const int* in_sizes, int n_in,
                              void* d_out, int out_size) {
    const float* hs   = (const float*)d_in[0];
    const int*   hlen = (const int*)d_in[1];
    const int*   ys   = (const int*)d_in[2];
    const int*   ylen = (const int*)d_in[3];
    const float* Wm   = (const float*)d_in[4];
    const float* bias = (const float*)d_in[5];
    float* out = (float*)d_out;

    static bool attrs_set = false;
    if (!attrs_set) {
        cudaFuncSetAttribute(gemm_mma_kernel, cudaFuncAttributeMaxDynamicSharedMemorySize, GEMM_SMEM);
        cudaFuncSetAttribute(ctc_dp_kernel, cudaFuncAttributeMaxDynamicSharedMemorySize, Tn * Jn * 4);
        attrs_set = true;
    }

    prep_kernel<<<6161, 256>>>(hs, Wm, ys);
    gemm_mma_kernel<<<dim3(Vn / 128, Mn / 64), 256, GEMM_SMEM>>>(ys, bias);
    lse_emit_kernel<<<Mn / 8, 256>>>();
    ctc_dp_kernel<<<Bn, 160, Tn * Jn * 4>>>(ys, hlen, ylen, out);
}

// round 10
// speedup vs baseline: 1.1311x; 1.1311x over previous
#include <cuda_runtime.h>
#include <cuda_bf16.h>
#include <math.h>
#include <stdint.h>

// ---------------------------------------------------------------- shapes
constexpr int Bn = 16, Tn = 512, Hn = 512, Vn = 4096, Ln = 64, Jn = 66;
constexpr int Mn = Bn * Tn;            // 8192 GEMM rows
constexpr int Smax = 2 * Ln + 1;       // 129 CTC states
constexpr float NEGF = -1e30f;
constexpr float LOG2E = 1.4426950408889634f;
constexpr float LN2 = 0.6931471805599453f;

// ---------------------------------------------------------------- scratch
__device__ __nv_bfloat16 g_Abf[(size_t)Mn * Hn];    // 8 MB
__device__ __nv_bfloat16 g_Bbf[(size_t)Vn * Hn];    // 4 MB  W^T [V,K] K-major
__device__ float2        g_part[(size_t)Mn * 64];   // per-row (max,sumexp) partials
__device__ float         g_gath[(size_t)Mn * Jn];   // gathered logits at label ids
__device__ float         g_emit[(size_t)Mn * Jn];   // log2-domain emissions
__device__ int           g_rep[Bn * Jn];            // duplicate-label representative
__device__ float         g_ll[Bn];
__device__ int           g_ctr;

// ---------------------------------------------------------------- helpers
__device__ __forceinline__ uint32_t smem_u32(const void* p) {
    uint32_t a;
    asm("{ .reg .u64 t; cvta.to.shared.u64 t, %1; cvt.u32.u64 %0, t; }" : "=r"(a) : "l"(p));
    return a;
}
__device__ __forceinline__ void ldm_x4(uint32_t* r, uint32_t addr) {
    asm volatile("ldmatrix.sync.aligned.m8n8.x4.shared.b16 {%0,%1,%2,%3}, [%4];"
                 : "=r"(r[0]), "=r"(r[1]), "=r"(r[2]), "=r"(r[3]) : "r"(addr));
}
__device__ __forceinline__ void mma_bf16(float* d, const uint32_t* a, const uint32_t* b) {
    asm volatile("mma.sync.aligned.m16n8k16.row.col.f32.bf16.bf16.f32 "
                 "{%0,%1,%2,%3}, {%4,%5,%6,%7}, {%8,%9}, {%0,%1,%2,%3};"
                 : "+f"(d[0]), "+f"(d[1]), "+f"(d[2]), "+f"(d[3])
                 : "r"(a[0]), "r"(a[1]), "r"(a[2]), "r"(a[3]), "r"(b[0]), "r"(b[1]));
}
__device__ __forceinline__ float ex2(float x) {
    float r; asm("ex2.approx.ftz.f32 %0, %1;" : "=f"(r) : "f"(x)); return r;
}
__device__ __forceinline__ float lg2(float x) {
    float r; asm("lg2.approx.f32 %0, %1;" : "=f"(r) : "f"(x)); return r;
}
#define CP_ASYNC16(dst, src) \
    asm volatile("cp.async.cg.shared.global [%0], [%1], 16;" :: "r"(dst), "l"(src) : "memory")
#define CP_COMMIT() asm volatile("cp.async.commit_group;" ::: "memory")
#define CP_WAIT2()  asm volatile("cp.async.wait_group 2;" ::: "memory")

// ---------------------------------------------------------------- fused preprocessing
__global__ __launch_bounds__(256) void prep_kernel(const float* __restrict__ hs,
                                                   const float* __restrict__ W,
                                                   const int* __restrict__ ys) {
    const int bid = blockIdx.x, tid = threadIdx.x;
    if (bid < 4096) {
        size_t i = (size_t)bid * 256 + tid;
        float4 v = ((const float4*)hs)[i];
        __nv_bfloat162 lo = __floats2bfloat162_rn(v.x, v.y);
        __nv_bfloat162 hi = __floats2bfloat162_rn(v.z, v.w);
        uint2 u;
        u.x = *(uint32_t*)&lo;
        u.y = *(uint32_t*)&hi;
        ((uint2*)g_Abf)[i] = u;
    } else if (bid < 6144) {
        __shared__ float tile[32][33];
        const int vb = bid - 4096;
        const int v0 = (vb & 127) * 32, k0 = (vb >> 7) * 32;
        const int tx = tid & 31, ty = tid >> 5;
#pragma unroll
        for (int j = 0; j < 4; j++)
            tile[ty + 8 * j][tx] = W[(size_t)(k0 + ty + 8 * j) * Vn + v0 + tx];
        __syncthreads();
#pragma unroll
        for (int j = 0; j < 4; j++) {
            int vl = ty + 8 * j;
            g_Bbf[(size_t)(v0 + vl) * Hn + k0 + tx] = __float2bfloat16(tile[tx][vl]);
        }
    } else if (bid < 6160) {
        const int b = bid - 6144;
        const int j = tid;
        if (j < 65) {
            const int vid = (j == 0) ? 0 : ys[b * Ln + j - 1];
            int r = j;
            for (int q = 0; q < j; q++) {
                const int vq = (q == 0) ? 0 : ys[b * Ln + q - 1];
                if (vq == vid) { r = q; break; }
            }
            g_rep[b * Jn + j] = r;
        }
    } else {
        if (tid == 0) g_ctr = 0;
    }
}

// ---------------------------------------------------------------- HMMA GEMM
// CTA tile 128x128, BK=32, 128 threads = 4 warps of 64x64 (2x2 grid).
// 4-stage cp.async, 2 CTAs/SM. Smem/stage: A[4 kq(16B)][128 rows]=8KB, B same at +8192.
constexpr int STAGES = 4;
constexpr int STAGE_BYTES = 16384;
constexpr int GEMM_SMEM = STAGES * STAGE_BYTES;   // 64 KB

__global__ __launch_bounds__(128, 2) void gemm_mma_kernel(const int* __restrict__ ys,
                                                          const float* __restrict__ bias) {
    extern __shared__ __align__(1024) char sm[];
    __shared__ float sbias[128];
    __shared__ int stable[128];

    const int tid = threadIdx.x, w = tid >> 5, lane = tid & 31;
    const int bn = blockIdx.x * 128, bm = blockIdx.y * 128;
    const int b = blockIdx.y >> 2;

    if (tid < 128) { sbias[tid] = bias[bn + tid]; stable[tid] = -1; }
    __syncthreads();
    if (tid == 0) {
        for (int j = 0; j < 65; j++) {
            const int vid = (j == 0) ? 0 : ys[b * Ln + j - 1];
            const int idx = vid - bn;
            if (idx >= 0 && idx < 128 && stable[idx] < 0) stable[idx] = j;
        }
    }

    // cp.async mapping: thread tid owns row tid for both A and B; 4 x 16B each.
    const __nv_bfloat16* gA = g_Abf + (size_t)(bm + tid) * Hn;
    const __nv_bfloat16* gB = g_Bbf + (size_t)(bn + tid) * Hn;
    const uint32_t smb = smem_u32(sm);
    const uint32_t stsA = smb + (uint32_t)tid * 16;          // + i*2048 for kq i
    const uint32_t stsB = smb + 8192 + (uint32_t)tid * 16;

    // warp grid 2x2: wm = w>>1, wn = w&1; warp tile 64x64
    const int wm = w >> 1, wn = w & 1;
    // A ldmatrix base: frag rows wm*64 + mi*16 + (lane&15); kq selected by lane>>4 (+kk*2)
    const uint32_t aBase = smb + (uint32_t)(lane >> 4) * 2048
                         + (uint32_t)(wm * 64 + (lane & 15)) * 16;
    // B ldmatrix base (x4 = two n-frags x two kq):
    //   group g = lane>>3: kq = (g&1)+kk*2 ; row = wn*64 + pair*16 + (g>>1)*8 + (lane&7)
    const uint32_t bBase = smb + 8192 + (uint32_t)((lane >> 3) & 1) * 2048
                         + (uint32_t)(wn * 64 + ((lane >> 4) & 1) * 8 + (lane & 7)) * 16;

    float acc[4][8][4];
#pragma unroll
    for (int mi = 0; mi < 4; mi++)
#pragma unroll
        for (int ni = 0; ni < 8; ni++)
#pragma unroll
            for (int e = 0; e < 4; e++) acc[mi][ni][e] = 0.f;

    const int NC = Hn / 32;  // 16

#define ISSUE_STAGE(slot, c)                                                   \
    do {                                                                       \
        const uint32_t so = (uint32_t)(slot) * STAGE_BYTES;                    \
        _Pragma("unroll")                                                      \
        for (int i = 0; i < 4; i++) {                                          \
            CP_ASYNC16(stsA + so + i * 2048, gA + (c) * 32 + i * 8);           \
            CP_ASYNC16(stsB + so + i * 2048, gB + (c) * 32 + i * 8);           \
        }                                                                      \
    } while (0)

#pragma unroll
    for (int c = 0; c < 3; c++) { ISSUE_STAGE(c, c); CP_COMMIT(); }

    for (int c = 0; c < NC; c++) {
        CP_WAIT2();
        __syncthreads();
        if (c + 3 < NC) ISSUE_STAGE((c + 3) & (STAGES - 1), c + 3);
        CP_COMMIT();

        const uint32_t so = (uint32_t)(c & (STAGES - 1)) * STAGE_BYTES;
#pragma unroll
        for (int kk = 0; kk < 2; kk++) {
            uint32_t aF[4][4];
            uint32_t bF[8][2];
#pragma unroll
            for (int mi = 0; mi < 4; mi++)
                ldm_x4(aF[mi], aBase + so + kk * 4096 + mi * 256);
#pragma unroll
            for (int pair = 0; pair < 4; pair++) {
                uint32_t q[4];
                ldm_x4(q, bBase + so + kk * 4096 + pair * 256);
                bF[pair * 2 + 0][0] = q[0]; bF[pair * 2 + 0][1] = q[1];
                bF[pair * 2 + 1][0] = q[2]; bF[pair * 2 + 1][1] = q[3];
            }
#pragma unroll
            for (int mi = 0; mi < 4; mi++)
#pragma unroll
                for (int ni = 0; ni < 8; ni++)
                    mma_bf16(acc[mi][ni], aF[mi], bF[ni]);
        }
    }

    // ---- fused epilogue: bias, row (max,sumexp) partials, label gather
    const int tq = lane >> 2, lq = lane & 3;
#pragma unroll
    for (int mi = 0; mi < 4; mi++) {
#pragma unroll
        for (int h = 0; h < 2; h++) {
            const int rloc = wm * 64 + mi * 16 + h * 8 + tq;
            const size_t grow = (size_t)(bm + rloc);
            float v[16];
            float mx = -3.4e38f;
#pragma unroll
            for (int ni = 0; ni < 8; ni++)
#pragma unroll
                for (int e = 0; e < 2; e++) {
                    float f = acc[mi][ni][h * 2 + e] + sbias[wn * 64 + ni * 8 + lq * 2 + e];
                    v[ni * 2 + e] = f;
                    mx = fmaxf(mx, f);
                }
            float sum = 0.f;
#pragma unroll
            for (int i = 0; i < 16; i++) sum += __expf(v[i] - mx);
#pragma unroll
            for (int o = 1; o <= 2; o <<= 1) {
                float mo = __shfl_xor_sync(0xffffffffu, mx, o);
                float so2 = __shfl_xor_sync(0xffffffffu, sum, o);
                float m2 = fmaxf(mx, mo);
                sum = sum * __expf(mx - m2) + so2 * __expf(mo - m2);
                mx = m2;
            }
            if (lq == 0)
                g_part[grow * 64 + blockIdx.x * 2 + wn] = make_float2(mx, sum);
#pragma unroll
            for (int ni = 0; ni < 8; ni++)
#pragma unroll
                for (int e = 0; e < 2; e++) {
                    const int cidx = wn * 64 + ni * 8 + lq * 2 + e;
                    const int slot = stable[cidx];
                    if (slot >= 0) g_gath[grow * Jn + slot] = v[ni * 2 + e];
                }
        }
    }
}

// ---------------------------------------------------------------- LSE reduce (64 partials/row) + emit
__global__ __launch_bounds__(256) void lse_emit_kernel() {
    const int warp = threadIdx.x >> 5, lane = threadIdx.x & 31;
    const size_t row = (size_t)blockIdx.x * 8 + warp;
    const int b = (int)(row >> 9);
    float2 p0 = g_part[row * 64 + lane];
    float2 p1 = g_part[row * 64 + 32 + lane];
    float m = fmaxf(p0.x, p1.x);
#pragma unroll
    for (int o = 16; o > 0; o >>= 1) m = fmaxf(m, __shfl_xor_sync(0xffffffffu, m, o));
    float s = p0.y * __expf(p0.x - m) + p1.y * __expf(p1.x - m);
#pragma unroll
    for (int o = 16; o > 0; o >>= 1) s += __shfl_xor_sync(0xffffffffu, s, o);
    const float lse = m + __logf(s);
#pragma unroll
    for (int j = lane; j < 65; j += 32)
        g_emit[row * Jn + j] = (g_gath[row * Jn + g_rep[b * Jn + j]] - lse) * LOG2E;
}

// ---------------------------------------------------------------- CTC DP: halo-4 wavefront (R6 winner)
__global__ __launch_bounds__(160) void ctc_dp_kernel(const int* __restrict__ ys,
                                                     const int* __restrict__ hlen,
                                                     const int* __restrict__ ylen,
                                                     float* __restrict__ out) {
    extern __shared__ float sem[];
    __shared__ float sbuf[2][20];
    __shared__ float sal[Smax + 12];

    const int b = blockIdx.x, tid = threadIdx.x;
    const int w = tid >> 5, lane = tid & 31;
    const int s = w * 28 + lane - 4;
    const int inlen = hlen[b];

    {
        const float2* src = (const float2*)(g_emit + (size_t)b * Tn * Jn);
        float2* dst = (float2*)sem;
        const int n2 = inlen * (Jn / 2);
        for (int i = tid; i < n2; i += 160) dst[i] = src[i];
    }

    int jj = 0;
    bool skipv = false;
    if (s >= 0 && s < Smax && (s & 1)) {
        const int li = (s - 1) >> 1;
        jj = li + 1;
        const int lab = ys[b * Ln + li];
        if (s >= 3) skipv = (lab != 0) && (lab != ys[b * Ln + li - 1]);
    }
    __syncthreads();

    float a = (s == 0) ? sem[0] : (s == 1) ? sem[1] : NEGF;
    int pb = 0;
    if (lane >= 28) sbuf[0][w * 4 + lane - 28] = a;
    __syncthreads();

    for (int t = 1; t < inlen; t += 2) {
        if (lane < 4) a = (w > 0) ? sbuf[pb][(w - 1) * 4 + lane] : NEGF;
        {
            const float e = sem[t * Jn + jj];
            const float up1 = __shfl_up_sync(0xffffffffu, a, 1);
            const float up2 = __shfl_up_sync(0xffffffffu, a, 2);
            const float am2 = skipv ? up2 : NEGF;
            const float m = fmaxf(fmaxf(a, up1), am2);
            a = m + lg2(ex2(a - m) + ex2(up1 - m) + ex2(am2 - m)) + e;
        }
        if (t + 1 < inlen) {
            const float e = sem[(t + 1) * Jn + jj];
            const float up1 = __shfl_up_sync(0xffffffffu, a, 1);
            const float up2 = __shfl_up_sync(0xffffffffu, a, 2);
            const float am2 = skipv ? up2 : NEGF;
            const float m = fmaxf(fmaxf(a, up1), am2);
            a = m + lg2(ex2(a - m) + ex2(up1 - m) + ex2(am2 - m)) + e;
        }
        pb ^= 1;
        if (lane >= 28) sbuf[pb][w * 4 + lane - 28] = a;
        __syncthreads();
    }

    if (lane >= 4 && s < Smax) sal[s] = a;
    __syncthreads();
    if (tid == 0) {
        const int s2 = 2 * ylen[b];
        const float x = sal[s2], y = sal[s2 - 1];
        const float m = fmaxf(x, y), d = fminf(x, y) - m;
        g_ll[b] = -(m + lg2(1.f + ex2(d))) * LN2;
        __threadfence();
        const int done = atomicAdd(&g_ctr, 1);
        if (done == Bn - 1) {
            float acc = 0.f;
#pragma unroll
            for (int i = 0; i < Bn; i++) acc += g_ll[i];
            out[0] = acc / (float)Bn;
        }
    }
}

// ----------------------------------------------------------------
extern "C" void kernel_launch(void* const* d_in, const int* in_sizes, int n_in,
                              void* d_out, int out_size) {
    const float* hs   = (const float*)d_in[0];
    const int*   hlen = (const int*)d_in[1];
    const int*   ys   = (const int*)d_in[2];
    const int*   ylen = (const int*)d_in[3];
    const float* Wm   = (const float*)d_in[4];
    const float* bias = (const float*)d_in[5];
    float* out = (float*)d_out;

    static bool attrs_set = false;
    if (!attrs_set) {
        cudaFuncSetAttribute(gemm_mma_kernel, cudaFuncAttributeMaxDynamicSharedMemorySize, GEMM_SMEM);
        cudaFuncSetAttribute(ctc_dp_kernel, cudaFuncAttributeMaxDynamicSharedMemorySize, Tn * Jn * 4);
        attrs_set = true;
    }

    prep_kernel<<<6161, 256>>>(hs, Wm, ys);
    gemm_mma_kernel<<<dim3(Vn / 128, Mn / 128), 128, GEMM_SMEM>>>(ys, bias);
    lse_emit_kernel<<<Mn / 8, 256>>>();
    ctc_dp_kernel<<<Bn, 160, Tn * Jn * 4>>>(ys, hlen, ylen, out);
}

// round 11
// speedup vs baseline: 1.2898x; 1.1403x over previous
#include <cuda_runtime.h>
#include <cuda_bf16.h>
#include <cuda_fp8.h>
#include <math.h>
#include <stdint.h>

// ---------------------------------------------------------------- shapes
constexpr int Bn = 16, Tn = 512, Hn = 512, Vn = 4096, Ln = 64, Jn = 66;
constexpr int Mn = Bn * Tn;            // 8192 GEMM rows
constexpr int Smax = 2 * Ln + 1;       // 129 CTC states
constexpr float NEGF = -1e30f;
constexpr float LOG2E = 1.4426950408889634f;
constexpr float LN2 = 0.6931471805599453f;
constexpr float WSCALE = 16.0f;        // W pre-scale into e4m3 normal range
constexpr float INV_WSCALE = 1.0f / 16.0f;

// ---------------------------------------------------------------- scratch
__device__ uint8_t g_A8[(size_t)Mn * Hn];           // 4 MB  e4m3 activations
__device__ uint8_t g_B8[(size_t)Vn * Hn];           // 2 MB  e4m3 W^T [V,K] K-major (x16)
__device__ float2  g_part[(size_t)Mn * 128];        // per-row (max,sumexp) partials
__device__ float   g_gath[(size_t)Mn * Jn];         // gathered logits at label ids
__device__ float   g_emit[(size_t)Mn * Jn];         // log2-domain emissions
__device__ int     g_rep[Bn * Jn];                  // duplicate-label representative
__device__ float   g_ll[Bn];
__device__ int     g_ctr;

// ---------------------------------------------------------------- helpers
__device__ __forceinline__ uint32_t smem_u32(const void* p) {
    uint32_t a;
    asm("{ .reg .u64 t; cvta.to.shared.u64 t, %1; cvt.u32.u64 %0, t; }" : "=r"(a) : "l"(p));
    return a;
}
__device__ __forceinline__ void ldm_x4(uint32_t* r, uint32_t addr) {
    asm volatile("ldmatrix.sync.aligned.m8n8.x4.shared.b16 {%0,%1,%2,%3}, [%4];"
                 : "=r"(r[0]), "=r"(r[1]), "=r"(r[2]), "=r"(r[3]) : "r"(addr));
}
__device__ __forceinline__ void ldm_x2(uint32_t* r, uint32_t addr) {
    asm volatile("ldmatrix.sync.aligned.m8n8.x2.shared.b16 {%0,%1}, [%2];"
                 : "=r"(r[0]), "=r"(r[1]) : "r"(addr));
}
__device__ __forceinline__ void mma_fp8(float* d, const uint32_t* a, const uint32_t* b) {
    asm volatile("mma.sync.aligned.m16n8k32.row.col.f32.e4m3.e4m3.f32 "
                 "{%0,%1,%2,%3}, {%4,%5,%6,%7}, {%8,%9}, {%0,%1,%2,%3};"
                 : "+f"(d[0]), "+f"(d[1]), "+f"(d[2]), "+f"(d[3])
                 : "r"(a[0]), "r"(a[1]), "r"(a[2]), "r"(a[3]), "r"(b[0]), "r"(b[1]));
}
__device__ __forceinline__ float ex2(float x) {
    float r; asm("ex2.approx.ftz.f32 %0, %1;" : "=f"(r) : "f"(x)); return r;
}
__device__ __forceinline__ float lg2(float x) {
    float r; asm("lg2.approx.f32 %0, %1;" : "=f"(r) : "f"(x)); return r;
}
__device__ __forceinline__ uint16_t f2_to_e4m3x2(float x, float y) {
    return (uint16_t)__nv_cvt_float2_to_fp8x2(make_float2(x, y), __NV_SATFINITE, __NV_E4M3);
}
#define CP_ASYNC16(dst, src) \
    asm volatile("cp.async.cg.shared.global [%0], [%1], 16;" :: "r"(dst), "l"(src) : "memory")
#define CP_COMMIT() asm volatile("cp.async.commit_group;" ::: "memory")
#define CP_WAIT2()  asm volatile("cp.async.wait_group 2;" ::: "memory")

// ---------------------------------------------------------------- fused preprocessing
// blocks [0,4096): convA fp32->e4m3 ; [4096,6144): convB transpose+convert(x16) ; [6144,6160): rep ; 6160: ctr
__global__ __launch_bounds__(256) void prep_kernel(const float* __restrict__ hs,
                                                   const float* __restrict__ W,
                                                   const int* __restrict__ ys) {
    const int bid = blockIdx.x, tid = threadIdx.x;
    if (bid < 4096) {
        size_t i = (size_t)bid * 256 + tid;
        float4 v = ((const float4*)hs)[i];
        uint32_t u = (uint32_t)f2_to_e4m3x2(v.x, v.y) | ((uint32_t)f2_to_e4m3x2(v.z, v.w) << 16);
        ((uint32_t*)g_A8)[i] = u;
    } else if (bid < 6144) {
        __shared__ float tile[32][33];
        const int vb = bid - 4096;
        const int v0 = (vb & 127) * 32, k0 = (vb >> 7) * 32;
        const int tx = tid & 31, ty = tid >> 5;
#pragma unroll
        for (int j = 0; j < 4; j++)
            tile[ty + 8 * j][tx] = W[(size_t)(k0 + ty + 8 * j) * Vn + v0 + tx];
        __syncthreads();
#pragma unroll
        for (int j = 0; j < 4; j++) {
            int vl = ty + 8 * j;
            __nv_fp8_e4m3 q(tile[tx][vl] * WSCALE);
            g_B8[(size_t)(v0 + vl) * Hn + k0 + tx] = *(uint8_t*)&q;
        }
    } else if (bid < 6160) {
        const int b = bid - 6144;
        const int j = tid;
        if (j < 65) {
            const int vid = (j == 0) ? 0 : ys[b * Ln + j - 1];
            int r = j;
            for (int q = 0; q < j; q++) {
                const int vq = (q == 0) ? 0 : ys[b * Ln + q - 1];
                if (vq == vid) { r = q; break; }
            }
            g_rep[b * Jn + j] = r;
        }
    } else {
        if (tid == 0) g_ctr = 0;
    }
}

// ---------------------------------------------------------------- FP8 MMA GEMM (R6 structure, k32 MMA)
// CTA tile 128x128, BK=64 (fp8), 8 warps (warp tile 64x32), 4-stage cp.async.
// Smem/stage: A[4 sub(16B)][128 rows]=8KB at +0, B same at +8192. 16KB/stage.
constexpr int STAGES = 4;
constexpr int STAGE_BYTES = 16384;
constexpr int GEMM_SMEM = STAGES * STAGE_BYTES;   // 64 KB -> 2 CTAs/SM

__global__ __launch_bounds__(256, 2) void gemm_mma_kernel(const int* __restrict__ ys,
                                                          const float* __restrict__ bias) {
    extern __shared__ __align__(1024) char sm[];
    __shared__ float sbias[128];
    __shared__ int stable[128];

    const int tid = threadIdx.x, w = tid >> 5, lane = tid & 31;
    const int bn = blockIdx.x * 128, bm = blockIdx.y * 128;
    const int b = blockIdx.y >> 2;

    if (tid < 128) { sbias[tid] = bias[bn + tid]; stable[tid] = -1; }
    __syncthreads();
    if (tid == 0) {
        for (int j = 0; j < 65; j++) {
            const int vid = (j == 0) ? 0 : ys[b * Ln + j - 1];
            const int idx = vid - bn;
            if (idx >= 0 && idx < 128 && stable[idx] < 0) stable[idx] = j;
        }
    }

    // cp.async mapping: 2 threads/row, each 2 x 16B per operand per chunk (64B rows)
    const int row = tid >> 1, kp = tid & 1;
    const uint8_t* gA = g_A8 + (size_t)(bm + row) * Hn + kp * 16;
    const uint8_t* gB = g_B8 + (size_t)(bn + row) * Hn + kp * 16;
    const uint32_t smb = smem_u32(sm);
    const uint32_t stsA = smb + (uint32_t)(kp * 2) * 2048 + (uint32_t)row * 16;

    // ldmatrix bases (same pattern as bf16-k16: one 16B sub-chunk = k16 fp8)
    const int wm = w >> 2, wn = w & 3;
    const uint32_t aBase = smb + (uint32_t)(wm * 64 + (lane & 15)) * 16 + (uint32_t)(lane >> 4) * 2048;
    const uint32_t bBase = smb + 8192 + (uint32_t)(wn * 32 + (lane & 7)) * 16 + (uint32_t)((lane >> 3) & 1) * 2048;

    float acc[4][4][4];
#pragma unroll
    for (int mi = 0; mi < 4; mi++)
#pragma unroll
        for (int ni = 0; ni < 4; ni++)
#pragma unroll
            for (int e = 0; e < 4; e++) acc[mi][ni][e] = 0.f;

    const int NC = Hn / 64;  // 8 chunks of k64

#define ISSUE_STAGE(slot, c)                                                   \
    do {                                                                       \
        const uint32_t so = (uint32_t)(slot) * STAGE_BYTES;                    \
        _Pragma("unroll")                                                      \
        for (int i = 0; i < 2; i++) {                                          \
            CP_ASYNC16(stsA + so + i * 2048, gA + (c) * 64 + i * 32);          \
            CP_ASYNC16(stsA + so + 8192 + i * 2048, gB + (c) * 64 + i * 32);   \
        }                                                                      \
    } while (0)

#pragma unroll
    for (int c = 0; c < 3; c++) { ISSUE_STAGE(c, c); CP_COMMIT(); }

    for (int c = 0; c < NC; c++) {
        CP_WAIT2();
        __syncthreads();
        if (c + 3 < NC) ISSUE_STAGE((c + 3) & (STAGES - 1), c + 3);
        CP_COMMIT();

        const uint32_t so = (uint32_t)(c & (STAGES - 1)) * STAGE_BYTES;
#pragma unroll
        for (int kk = 0; kk < 2; kk++) {   // each kk-half = 2 sub-chunks = k32
            uint32_t aF[4][4], bF[4][2];
#pragma unroll
            for (int mi = 0; mi < 4; mi++)
                ldm_x4(aF[mi], aBase + so + kk * 4096 + mi * 256);
#pragma unroll
            for (int ni = 0; ni < 4; ni++)
                ldm_x2(bF[ni], bBase + so + kk * 4096 + ni * 128);
#pragma unroll
            for (int mi = 0; mi < 4; mi++)
#pragma unroll
                for (int ni = 0; ni < 4; ni++)
                    mma_fp8(acc[mi][ni], aF[mi], bF[ni]);
        }
    }

    // ---- fused epilogue: rescale + bias, row (max,sumexp) partials, label gather
    const int tq = lane >> 2, lq = lane & 3;
#pragma unroll
    for (int mi = 0; mi < 4; mi++) {
#pragma unroll
        for (int h = 0; h < 2; h++) {
            const int rloc = wm * 64 + mi * 16 + h * 8 + tq;
            const size_t grow = (size_t)(bm + rloc);
            float v[8];
            float mx = -3.4e38f;
#pragma unroll
            for (int ni = 0; ni < 4; ni++)
#pragma unroll
                for (int e = 0; e < 2; e++) {
                    float f = acc[mi][ni][h * 2 + e] * INV_WSCALE + sbias[wn * 32 + ni * 8 + lq * 2 + e];
                    v[ni * 2 + e] = f;
                    mx = fmaxf(mx, f);
                }
            float sum = 0.f;
#pragma unroll
            for (int i = 0; i < 8; i++) sum += __expf(v[i] - mx);
#pragma unroll
            for (int o = 1; o <= 2; o <<= 1) {
                float mo = __shfl_xor_sync(0xffffffffu, mx, o);
                float so2 = __shfl_xor_sync(0xffffffffu, sum, o);
                float m2 = fmaxf(mx, mo);
                sum = sum * __expf(mx - m2) + so2 * __expf(mo - m2);
                mx = m2;
            }
            if (lq == 0)
                g_part[grow * 128 + blockIdx.x * 4 + wn] = make_float2(mx, sum);
#pragma unroll
            for (int ni = 0; ni < 4; ni++)
#pragma unroll
                for (int e = 0; e < 2; e++) {
                    const int cidx = wn * 32 + ni * 8 + lq * 2 + e;
                    const int slot = stable[cidx];
                    if (slot >= 0) g_gath[grow * Jn + slot] = v[ni * 2 + e];
                }
        }
    }
}

// ---------------------------------------------------------------- LSE reduce (128 partials/row) + emit
__global__ __launch_bounds__(256) void lse_emit_kernel() {
    const int warp = threadIdx.x >> 5, lane = threadIdx.x & 31;
    const size_t row = (size_t)blockIdx.x * 8 + warp;
    const int b = (int)(row >> 9);
    float2 p[4];
#pragma unroll
    for (int i = 0; i < 4; i++) p[i] = g_part[row * 128 + lane + 32 * i];
    float m = fmaxf(fmaxf(p[0].x, p[1].x), fmaxf(p[2].x, p[3].x));
#pragma unroll
    for (int o = 16; o > 0; o >>= 1) m = fmaxf(m, __shfl_xor_sync(0xffffffffu, m, o));
    float s = 0.f;
#pragma unroll
    for (int i = 0; i < 4; i++) s += p[i].y * __expf(p[i].x - m);
#pragma unroll
    for (int o = 16; o > 0; o >>= 1) s += __shfl_xor_sync(0xffffffffu, s, o);
    const float lse = m + __logf(s);
#pragma unroll
    for (int j = lane; j < 65; j += 32)
        g_emit[row * Jn + j] = (g_gath[row * Jn + g_rep[b * Jn + j]] - lse) * LOG2E;
}

// ---------------------------------------------------------------- CTC DP: halo-4 wavefront (R6 winner)
__global__ __launch_bounds__(160) void ctc_dp_kernel(const int* __restrict__ ys,
                                                     const int* __restrict__ hlen,
                                                     const int* __restrict__ ylen,
                                                     float* __restrict__ out) {
    extern __shared__ float sem[];
    __shared__ float sbuf[2][20];
    __shared__ float sal[Smax + 12];

    const int b = blockIdx.x, tid = threadIdx.x;
    const int w = tid >> 5, lane = tid & 31;
    const int s = w * 28 + lane - 4;
    const int inlen = hlen[b];

    {
        const float2* src = (const float2*)(g_emit + (size_t)b * Tn * Jn);
        float2* dst = (float2*)sem;
        const int n2 = inlen * (Jn / 2);
        for (int i = tid; i < n2; i += 160) dst[i] = src[i];
    }

    int jj = 0;
    bool skipv = false;
    if (s >= 0 && s < Smax && (s & 1)) {
        const int li = (s - 1) >> 1;
        jj = li + 1;
        const int lab = ys[b * Ln + li];
        if (s >= 3) skipv = (lab != 0) && (lab != ys[b * Ln + li - 1]);
    }
    __syncthreads();

    float a = (s == 0) ? sem[0] : (s == 1) ? sem[1] : NEGF;
    int pb = 0;
    if (lane >= 28) sbuf[0][w * 4 + lane - 28] = a;
    __syncthreads();

    for (int t = 1; t < inlen; t += 2) {
        if (lane < 4) a = (w > 0) ? sbuf[pb][(w - 1) * 4 + lane] : NEGF;
        {
            const float e = sem[t * Jn + jj];
            const float up1 = __shfl_up_sync(0xffffffffu, a, 1);
            const float up2 = __shfl_up_sync(0xffffffffu, a, 2);
            const float am2 = skipv ? up2 : NEGF;
            const float m = fmaxf(fmaxf(a, up1), am2);
            a = m + lg2(ex2(a - m) + ex2(up1 - m) + ex2(am2 - m)) + e;
        }
        if (t + 1 < inlen) {
            const float e = sem[(t + 1) * Jn + jj];
            const float up1 = __shfl_up_sync(0xffffffffu, a, 1);
            const float up2 = __shfl_up_sync(0xffffffffu, a, 2);
            const float am2 = skipv ? up2 : NEGF;
            const float m = fmaxf(fmaxf(a, up1), am2);
            a = m + lg2(ex2(a - m) + ex2(up1 - m) + ex2(am2 - m)) + e;
        }
        pb ^= 1;
        if (lane >= 28) sbuf[pb][w * 4 + lane - 28] = a;
        __syncthreads();
    }

    if (lane >= 4 && s < Smax) sal[s] = a;
    __syncthreads();
    if (tid == 0) {
        const int s2 = 2 * ylen[b];
        const float x = sal[s2], y = sal[s2 - 1];
        const float m = fmaxf(x, y), d = fminf(x, y) - m;
        g_ll[b] = -(m + lg2(1.f + ex2(d))) * LN2;
        __threadfence();
        const int done = atomicAdd(&g_ctr, 1);
        if (done == Bn - 1) {
            float acc = 0.f;
#pragma unroll
            for (int i = 0; i < Bn; i++) acc += g_ll[i];
            out[0] = acc / (float)Bn;
        }
    }
}

// ----------------------------------------------------------------
extern "C" void kernel_launch(void* const* d_in, const int* in_sizes, int n_in,
                              void* d_out, int out_size) {
    const float* hs   = (const float*)d_in[0];
    const int*   hlen = (const int*)d_in[1];
    const int*   ys   = (const int*)d_in[2];
    const int*   ylen = (const int*)d_in[3];
    const float* Wm   = (const float*)d_in[4];
    const float* bias = (const float*)d_in[5];
    float* out = (float*)d_out;

    static bool attrs_set = false;
    if (!attrs_set) {
        cudaFuncSetAttribute(gemm_mma_kernel, cudaFuncAttributeMaxDynamicSharedMemorySize, GEMM_SMEM);
        cudaFuncSetAttribute(ctc_dp_kernel, cudaFuncAttributeMaxDynamicSharedMemorySize, Tn * Jn * 4);
        attrs_set = true;
    }

    prep_kernel<<<6161, 256>>>(hs, Wm, ys);
    gemm_mma_kernel<<<dim3(Vn / 128, Mn / 128), 256, GEMM_SMEM>>>(ys, bias);
    lse_emit_kernel<<<Mn / 8, 256>>>();
    ctc_dp_kernel<<<Bn, 160, Tn * Jn * 4>>>(ys, hlen, ylen, out);
}